// round 15
// baseline (speedup 1.0000x reference)
#include <cuda_runtime.h>
#include <cuda_fp16.h>
#include <cuda_bf16.h>
#include <math.h>

#define NU 50000
#define NI 100000
#define NN 150000
#define DD 64
#define BB 4096
#define EMAX 3150000
#define ETCAP (EMAX + NN + 16)   // padded rows (<=1 pad/row) + prefetch slack
#define NBLK 586                 // ceil(NN/256)

// ---------------- device scratch -------------------------------------------
__device__ float  d_deg[NN];             // dinv = deg^-0.5
__device__ float  d_rdeg[NN];            // sqrt(deg)
__device__ int    d_cnt[NN];             // counts -> cursors (reset by gather p0)
__device__ int    d_rowptr[NN];          // row start (even)
__device__ int    d_rend[NN];            // padded row end (even)
__device__ int    d_cursor = 0;          // global CSR allocation cursor
__device__ int    d_et[ETCAP];           // CSR-sorted target ids (pad -> NN zero row)
__device__ __half d_egoh[(NN + 1) * DD]; // s0 = dinv * ego ; row NN = zeros
__device__ __half d_curh[(NN + 1) * DD]; // s1              ; row NN = zeros
__device__ __half d_nxth[(NN + 1) * DD]; // s2              ; row NN = zeros
__device__ float  d_acc[NN * DD];
__device__ __half d_genH[2 * BB * DD];
__device__ __half d_intH[2 * BB * DD];
__device__ float  d_negS[2 * BB];        // zeroed by k_final after use
__device__ float  d_posS[2 * BB];
__device__ double d_sums[4];             // 0: kl, 1: bpr, 2: emb (zeroed by k_final)

__device__ __forceinline__ float softplus_f(float x) {
    return x > 0.f ? x + log1pf(expf(-x)) : log1pf(expf(x));
}

__device__ __forceinline__ unsigned smem_u32(const void* p) {
    return (unsigned)__cvta_generic_to_shared(p);
}

__device__ __forceinline__ void ldsm_x4(unsigned &r0, unsigned &r1, unsigned &r2, unsigned &r3, unsigned addr) {
    asm volatile("ldmatrix.sync.aligned.m8n8.x4.shared.b16 {%0,%1,%2,%3}, [%4];"
                 : "=r"(r0), "=r"(r1), "=r"(r2), "=r"(r3) : "r"(addr));
}
__device__ __forceinline__ void ldsm_x2(unsigned &r0, unsigned &r1, unsigned addr) {
    asm volatile("ldmatrix.sync.aligned.m8n8.x2.shared.b16 {%0,%1}, [%2];"
                 : "=r"(r0), "=r"(r1) : "r"(addr));
}
__device__ __forceinline__ void mma16816(float* c, unsigned a0, unsigned a1, unsigned a2, unsigned a3,
                                         unsigned b0, unsigned b1) {
    asm volatile("mma.sync.aligned.m16n8k16.row.col.f32.f16.f16.f32 "
                 "{%0,%1,%2,%3}, {%4,%5,%6,%7}, {%8,%9}, {%0,%1,%2,%3};"
                 : "+f"(c[0]), "+f"(c[1]), "+f"(c[2]), "+f"(c[3])
                 : "r"(a0), "r"(a1), "r"(a2), "r"(a3), "r"(b0), "r"(b1));
}

// ---------------- CSR build ------------------------------------------------
__global__ void k_count(const int4* __restrict__ h4, const int* __restrict__ h, int E) {
    int i = blockIdx.x * blockDim.x + threadIdx.x;
    int E4 = E >> 2;
    if (i < E4) {
        int4 q = __ldg(h4 + i);
        atomicAdd(&d_cnt[q.x], 1);
        atomicAdd(&d_cnt[q.y], 1);
        atomicAdd(&d_cnt[q.z], 1);
        atomicAdd(&d_cnt[q.w], 1);
    }
    int tail = E4 * 4 + i;
    if (i < (E & 3)) atomicAdd(&d_cnt[h[tail]], 1);
}

// block scan (even-padded counts) + atomic block base; write pad slots (zero-row
// index NN); zero row NN of the three half buffers; convert ego rows to half.
__global__ void k_scanfill(const float4* __restrict__ ue, const float4* __restrict__ ie) {
    __shared__ int sh[256];
    __shared__ int sbase;
    __shared__ float sdeg[256];
    int tid = threadIdx.x;
    int idx = blockIdx.x * 256 + tid;
    int c = (idx < NN) ? d_cnt[idx] : 0;
    int c2 = c + (c & 1);                // pad to even
    sh[tid] = c2;
    __syncthreads();
    for (int o = 1; o < 256; o <<= 1) {
        int x = sh[tid];
        if (tid >= o) x += sh[tid - o];
        __syncthreads();
        sh[tid] = x;
        __syncthreads();
    }
    if (tid == 255) sbase = atomicAdd(&d_cursor, sh[255]);
    __syncthreads();
    float dinv = rsqrtf((float)c);
    if (idx < NN) {
        int p = sbase + sh[tid] - c2;    // even base
        d_rowptr[idx] = p;
        d_rend[idx] = p + c2;            // padded end
        d_cnt[idx] = p;                  // cursor for binning (fills [p, p+c))
        if (c & 1) d_et[p + c] = NN;     // pad slot -> zero row
        d_deg[idx] = dinv;
        d_rdeg[idx] = sqrtf((float)c);
    }
    sdeg[tid] = dinv;
    if (blockIdx.x == 0 && tid < 24) {   // zero row NN (128B per buffer)
        uint4 z = make_uint4(0u, 0u, 0u, 0u);
        if (tid < 8)       ((uint4*)(d_egoh + NN * DD))[tid] = z;
        else if (tid < 16) ((uint4*)(d_curh + NN * DD))[tid - 8] = z;
        else               ((uint4*)(d_nxth + NN * DD))[tid - 16] = z;
    }
    __syncthreads();
    int base_node = blockIdx.x * 256;
    for (int i = tid; i < 4096; i += 256) {
        int node = base_node + (i >> 4);
        if (node >= NN) continue;
        int ch = i & 15;
        float4 v = (node < NU) ? __ldg(ue + (size_t)node * 16 + ch)
                               : __ldg(ie + (size_t)(node - NU) * 16 + ch);
        float s = sdeg[i >> 4];
        union { uint2 u; __half2 h[2]; } o;
        o.h[0] = __floats2half2_rn(s * v.x, s * v.y);
        o.h[1] = __floats2half2_rn(s * v.z, s * v.w);
        ((uint2*)d_egoh)[(size_t)node * 16 + ch] = o.u;
    }
}

__global__ void k_bin(const int4* __restrict__ h4, const int4* __restrict__ t4,
                      const int* __restrict__ h, const int* __restrict__ t, int E) {
    int i = blockIdx.x * blockDim.x + threadIdx.x;
    int E4 = E >> 2;
    if (i < E4) {
        int4 qh = __ldg(h4 + i);
        int4 qt = __ldg(t4 + i);
        d_et[atomicAdd(&d_cnt[qh.x], 1)] = qt.x;
        d_et[atomicAdd(&d_cnt[qh.y], 1)] = qt.y;
        d_et[atomicAdd(&d_cnt[qh.z], 1)] = qt.z;
        d_et[atomicAdd(&d_cnt[qh.w], 1)] = qt.w;
    }
    int tail = E4 * 4 + i;
    if (i < (E & 3)) d_et[atomicAdd(&d_cnt[h[tail]], 1)] = t[tail];
}

// ---------------- pull gather: warp/node, paired idx, HADD2 ----------------
template<int PASS>
__global__ void k_gather(const float4* __restrict__ ue, const float4* __restrict__ ie) {
    int node = (blockIdx.x * blockDim.x + threadIdx.x) >> 5;
    int lane = threadIdx.x & 31;
    int sub = lane >> 3, ch = lane & 7;
    int beg = __ldg(&d_rowptr[node]);
    int end2 = __ldg(&d_rend[node]);
    const char* __restrict__ src =
        (PASS == 0) ? (const char*)d_egoh :
        (PASS == 1) ? (const char*)d_curh : (const char*)d_nxth;
    const char* srcc = src + ((unsigned)ch << 4);
    __half2 z2 = __float2half2_rn(0.f);
    __half2 va0 = z2, va1 = z2, va2 = z2, va3 = z2;
    __half2 vb0 = z2, vb1 = z2, vb2 = z2, vb3 = z2;
    int e = beg + 2 * sub;                       // even -> int2-aligned
    int2 t = __ldg((const int2*)&d_et[e]);       // unconditional (padded array)
    while (e + 1 < end2) {
        union { uint4 u; __half2 h[4]; } x0, x1;
        x0.u = __ldg((const uint4*)(srcc + (size_t)t.x * 128));
        x1.u = __ldg((const uint4*)(srcc + (size_t)t.y * 128));
        e += 8;
        t = __ldg((const int2*)&d_et[e]);        // unconditional prefetch
        va0 = __hadd2(va0, x0.h[0]); va1 = __hadd2(va1, x0.h[1]);
        va2 = __hadd2(va2, x0.h[2]); va3 = __hadd2(va3, x0.h[3]);
        vb0 = __hadd2(vb0, x1.h[0]); vb1 = __hadd2(vb1, x1.h[1]);
        vb2 = __hadd2(vb2, x1.h[2]); vb3 = __hadd2(vb3, x1.h[3]);
    }
    float v[8];
    {
        float2 fa, fb;
        fa = __half22float2(va0); fb = __half22float2(vb0); v[0] = fa.x + fb.x; v[1] = fa.y + fb.y;
        fa = __half22float2(va1); fb = __half22float2(vb1); v[2] = fa.x + fb.x; v[3] = fa.y + fb.y;
        fa = __half22float2(va2); fb = __half22float2(vb2); v[4] = fa.x + fb.x; v[5] = fa.y + fb.y;
        fa = __half22float2(va3); fb = __half22float2(vb3); v[6] = fa.x + fb.x; v[7] = fa.y + fb.y;
    }
    // reduce across the 4 edge slots
    #pragma unroll
    for (int j = 0; j < 8; j++) {
        v[j] += __shfl_xor_sync(0xffffffffu, v[j], 8);
        v[j] += __shfl_xor_sync(0xffffffffu, v[j], 16);
    }
    float dinv = __ldg(&d_deg[node]);
    if (PASS == 0 && lane == 0) d_cnt[node] = 0;  // recycle for next replay
    if (sub != 0) return;
    if (PASS < 2) {
        float s = dinv * dinv;
        union { uint4 u; __half2 h[4]; } o;
        o.h[0] = __floats2half2_rn(s * v[0], s * v[1]);
        o.h[1] = __floats2half2_rn(s * v[2], s * v[3]);
        o.h[2] = __floats2half2_rn(s * v[4], s * v[5]);
        o.h[3] = __floats2half2_rn(s * v[6], s * v[7]);
        uint4* dst = (PASS == 0) ? (uint4*)d_curh : (uint4*)d_nxth;
        dst[(size_t)node * 8 + ch] = o.u;
    } else {
        float rd = __ldg(&d_rdeg[node]);
        union { uint4 u; __half2 h[4]; } a, b;
        a.u = __ldg((const uint4*)d_curh + (size_t)node * 8 + ch);
        b.u = __ldg((const uint4*)d_nxth + (size_t)node * 8 + ch);
        const float4* ego = (node < NU) ? (ue + (size_t)node * 16)
                                        : (ie + (size_t)(node - NU) * 16);
        float4 e0 = __ldg(ego + ch * 2);
        float4 e1 = __ldg(ego + ch * 2 + 1);
        float s12[8];
        {
            float2 f0 = __half22float2(a.h[0]), g0 = __half22float2(b.h[0]);
            float2 f1 = __half22float2(a.h[1]), g1 = __half22float2(b.h[1]);
            float2 f2 = __half22float2(a.h[2]), g2 = __half22float2(b.h[2]);
            float2 f3 = __half22float2(a.h[3]), g3 = __half22float2(b.h[3]);
            s12[0] = f0.x + g0.x; s12[1] = f0.y + g0.y;
            s12[2] = f1.x + g1.x; s12[3] = f1.y + g1.y;
            s12[4] = f2.x + g2.x; s12[5] = f2.y + g2.y;
            s12[6] = f3.x + g3.x; s12[7] = f3.y + g3.y;
        }
        float4 o0, o1;
        o0.x = e0.x + rd * s12[0] + dinv * v[0];
        o0.y = e0.y + rd * s12[1] + dinv * v[1];
        o0.z = e0.z + rd * s12[2] + dinv * v[2];
        o0.w = e0.w + rd * s12[3] + dinv * v[3];
        o1.x = e1.x + rd * s12[4] + dinv * v[4];
        o1.y = e1.y + rd * s12[5] + dinv * v[5];
        o1.z = e1.z + rd * s12[6] + dinv * v[6];
        o1.w = e1.w + rd * s12[7] + dinv * v[7];
        float4* ap = (float4*)(d_acc + (size_t)node * 64 + ch * 8);
        ap[0] = o0;
        ap[1] = o1;
    }
}

// ---------------- KL over all rows: lane-per-row, W broadcast --------------
__global__ __launch_bounds__(256) void k_kl(const float* __restrict__ lin_w,
                                            const float* __restrict__ lin_b) {
    __shared__ float sW[2048];   // [d][t] d*32+t
    __shared__ float sB[64];
    __shared__ float wsum[8];
    int tid = threadIdx.x;
    for (int i = tid; i < 2048; i += 256) sW[i] = lin_w[i];
    if (tid < 64) sB[tid] = lin_b[tid];
    __syncthreads();
    int row = blockIdx.x * 256 + tid;
    float kl = 0.f;
    if (row < NN) {
        const float4* ar = (const float4*)(d_acc + (size_t)row * 64);
        float4 c0[8];
        #pragma unroll
        for (int i = 0; i < 8; i++) c0[i] = __ldg(ar + i);
        float sp[32];
        #pragma unroll
        for (int i = 0; i < 8; i++) {
            sp[4*i+0] = softplus_f(c0[i].x);
            sp[4*i+1] = softplus_f(c0[i].y);
            sp[4*i+2] = softplus_f(c0[i].z);
            sp[4*i+3] = softplus_f(c0[i].w);
        }
        #pragma unroll
        for (int half = 0; half < 2; half++) {
            if (half) {
                #pragma unroll
                for (int i = 0; i < 8; i++) c0[i] = __ldg(ar + 8 + i);
            }
            #pragma unroll
            for (int dq = 0; dq < 8; dq++) {
                float am[4] = {c0[dq].x, c0[dq].y, c0[dq].z, c0[dq].w};
                #pragma unroll
                for (int dj = 0; dj < 4; dj++) {
                    int d = half * 32 + dq * 4 + dj;
                    float s = sB[d] + 1e-8f;
                    #pragma unroll
                    for (int t4 = 0; t4 < 8; t4++) {
                        float4 w = *(const float4*)&sW[d * 32 + t4 * 4];
                        s += sp[4*t4] * w.x + sp[4*t4+1] * w.y
                           + sp[4*t4+2] * w.z + sp[4*t4+3] * w.w;
                    }
                    float k = -0.5f * (1.f + 2.f * s - am[dj] * am[dj] - expf(2.f * s));
                    if (isfinite(k)) kl += k;
                }
            }
        }
    }
    #pragma unroll
    for (int o = 16; o; o >>= 1) kl += __shfl_xor_sync(0xffffffffu, kl, o);
    if ((tid & 31) == 0) wsum[tid >> 5] = kl;
    __syncthreads();
    if (tid == 0) {
        float s = 0.f;
        #pragma unroll
        for (int i = 0; i < 8; i++) s += wsum[i];
        atomicAdd(&d_sums[0], (double)s);
    }
}

__global__ void k_bpr_emb(const float* __restrict__ ue, const float* __restrict__ ie,
                          const int* __restrict__ users, const int* __restrict__ pos,
                          const int* __restrict__ neg) {
    __shared__ float sb[8], se[8];
    int w = threadIdx.x >> 5, lane = threadIdx.x & 31;
    int b = blockIdx.x * 8 + w;
    float bpr = 0.f, emb = 0.f;
    {
        int u = users[b], pi = pos[b], ni = neg[b];
        float u0 = d_acc[u * 64 + lane],         u1 = d_acc[u * 64 + 32 + lane];
        float p0 = d_acc[(NU + pi) * 64 + lane], p1 = d_acc[(NU + pi) * 64 + 32 + lane];
        float n0 = d_acc[(NU + ni) * 64 + lane], n1 = d_acc[(NU + ni) * 64 + 32 + lane];
        float dsc = (u0 * n0 + u1 * n1) - (u0 * p0 + u1 * p1);
        float r0 = ue[u * 64 + lane],  r1 = ue[u * 64 + 32 + lane];
        float q0 = ie[pi * 64 + lane], q1 = ie[pi * 64 + 32 + lane];
        float m0 = ie[ni * 64 + lane], m1 = ie[ni * 64 + 32 + lane];
        float sq = r0 * r0 + r1 * r1 + q0 * q0 + q1 * q1 + m0 * m0 + m1 * m1;
        #pragma unroll
        for (int o = 16; o; o >>= 1) {
            dsc += __shfl_xor_sync(0xffffffffu, dsc, o);
            sq  += __shfl_xor_sync(0xffffffffu, sq, o);
        }
        if (lane == 0) { bpr = softplus_f(dsc); emb = sq; }
    }
    if (lane == 0) { sb[w] = bpr; se[w] = emb; }
    __syncthreads();
    if (threadIdx.x == 0) {
        float s1 = 0.f, s2 = 0.f;
        for (int i = 0; i < 8; i++) { s1 += sb[i]; s2 += se[i]; }
        atomicAdd(&d_sums[1], (double)s1);
        atomicAdd(&d_sums[2], (double)s2);
    }
}

// ---------------- build CL rows: one warp per sample -----------------------
__global__ __launch_bounds__(128) void k_build_cl(
        const float* __restrict__ u_int_w, const float* __restrict__ i_int_w,
        const float* __restrict__ lin_w, const float* __restrict__ lin_b,
        const float* __restrict__ eps,
        const int* __restrict__ users, const int* __restrict__ pos) {
    __shared__ float sI[64 * 129];   // intent [d][k], pitch 129
    __shared__ float sW[64 * 33];    // lin_w  [d][t], pitch 33
    int tid = threadIdx.x;
    int s = blockIdx.y;
    const float* intent = s ? i_int_w : u_int_w;
    for (int i = tid; i < 8192; i += 128)
        sI[(i >> 7) * 129 + (i & 127)] = intent[i];
    for (int i = tid; i < 2048; i += 128)
        sW[(i >> 5) * 33 + (i & 31)] = lin_w[i];
    __syncthreads();

    int wid = tid >> 5, lane = tid & 31;
    float bb0 = __ldg(lin_b + lane), bb1 = __ldg(lin_b + 32 + lane);

    for (int it = 0; it < 4; it++) {
        int b = blockIdx.x * 16 + wid * 4 + it;
        int r = s ? (NU + pos[b]) : users[b];
        float a0 = d_acc[(size_t)r * 64 + lane];
        float a1 = d_acc[(size_t)r * 64 + 32 + lane];

        float lg0 = 0.f, lg1 = 0.f, lg2 = 0.f, lg3 = 0.f;
        #pragma unroll
        for (int d = 0; d < 64; d++) {
            float ad = __shfl_sync(0xffffffffu, (d < 32) ? a0 : a1, d & 31);
            const float* row = &sI[d * 129 + lane];
            lg0 += ad * row[0];
            lg1 += ad * row[32];
            lg2 += ad * row[64];
            lg3 += ad * row[96];
        }
        float mx = fmaxf(fmaxf(lg0, lg1), fmaxf(lg2, lg3));
        #pragma unroll
        for (int o = 16; o; o >>= 1) mx = fmaxf(mx, __shfl_xor_sync(0xffffffffu, mx, o));
        float p0 = expf(lg0 - mx), p1 = expf(lg1 - mx), p2 = expf(lg2 - mx), p3 = expf(lg3 - mx);
        float ps = p0 + p1 + p2 + p3;
        #pragma unroll
        for (int o = 16; o; o >>= 1) ps += __shfl_xor_sync(0xffffffffu, ps, o);
        float inv = 1.f / ps;
        p0 *= inv; p1 *= inv; p2 *= inv; p3 *= inv;

        float ov0 = 0.f, ov1 = 0.f;
        const float* r0p = &sI[lane * 129];
        const float* r1p = &sI[(lane + 32) * 129];
        #pragma unroll
        for (int k = 0; k < 32; k++) {
            float q0 = __shfl_sync(0xffffffffu, p0, k);
            float q1 = __shfl_sync(0xffffffffu, p1, k);
            float q2 = __shfl_sync(0xffffffffu, p2, k);
            float q3 = __shfl_sync(0xffffffffu, p3, k);
            ov0 += q0 * r0p[k] + q1 * r0p[32 + k] + q2 * r0p[64 + k] + q3 * r0p[96 + k];
            ov1 += q0 * r1p[k] + q1 * r1p[32 + k] + q2 * r1p[64 + k] + q3 * r1p[96 + k];
        }

        float sp = softplus_f(a0);
        float sd0 = 0.f, sd1 = 0.f;
        const float* w0p = &sW[lane * 33];
        const float* w1p = &sW[(lane + 32) * 33];
        #pragma unroll
        for (int t = 0; t < 32; t++) {
            float spt = __shfl_sync(0xffffffffu, sp, t);
            sd0 += spt * w0p[t];
            sd1 += spt * w1p[t];
        }
        sd0 += bb0 + 1e-8f;
        sd1 += bb1 + 1e-8f;
        float g0 = a0 + __ldg(eps + (size_t)r * 64 + lane) * sd0;
        float g1 = a1 + __ldg(eps + (size_t)r * 64 + 32 + lane) * sd1;

        float gn = g0 * g0 + g1 * g1;
        float on = ov0 * ov0 + ov1 * ov1;
        #pragma unroll
        for (int o = 16; o; o >>= 1) {
            gn += __shfl_xor_sync(0xffffffffu, gn, o);
            on += __shfl_xor_sync(0xffffffffu, on, o);
        }
        gn = rsqrtf(gn); on = rsqrtf(on);
        g0 *= gn; g1 *= gn; ov0 *= on; ov1 *= on;
        float pd = g0 * ov0 + g1 * ov1;
        #pragma unroll
        for (int o = 16; o; o >>= 1) pd += __shfl_xor_sync(0xffffffffu, pd, o);

        size_t ob = (size_t)(s * BB + b) * 64;
        d_genH[ob + lane] = __float2half(g0);
        d_genH[ob + 32 + lane] = __float2half(g1);
        d_intH[ob + lane] = __float2half(ov0);
        d_intH[ob + 32 + lane] = __float2half(ov1);
        if (lane == 0) d_posS[s * BB + b] = pd;
    }
}

// ---------------- InfoNCE denominators via HMMA ----------------------------
__global__ __launch_bounds__(256, 1) void k_infonce_mma() {
    __shared__ __align__(16) __half sA[128 * 64];
    __shared__ __align__(16) __half sB[128 * 64];
    int s = blockIdx.z;
    int r0 = blockIdx.x * 128;
    int c0 = blockIdx.y * 128;
    const uint4* __restrict__ A  = (const uint4*)(d_genH + (size_t)s * BB * 64);
    const uint4* __restrict__ Bm = (const uint4*)(d_intH + (size_t)s * BB * 64);
    int tid = threadIdx.x;
    unsigned baseA = smem_u32(sA), baseB = smem_u32(sB);

    for (int i = tid; i < 1024; i += 256) {
        int r = i >> 3, c = i & 7;
        unsigned off = (unsigned)(r * 128 + c * 16);
        off ^= (unsigned)((r & 7) << 4);
        *(uint4*)((char*)sA + off) = __ldg(A  + (size_t)(r0 + r) * 8 + c);
        *(uint4*)((char*)sB + off) = __ldg(Bm + (size_t)(c0 + r) * 8 + c);
    }
    __syncthreads();

    int wid = tid >> 5, lane = tid & 31;
    int wr = wid >> 2, wc = wid & 3;
    float acc[4][4][4];
    #pragma unroll
    for (int i = 0; i < 4; i++)
        #pragma unroll
        for (int j = 0; j < 4; j++)
            #pragma unroll
            for (int q = 0; q < 4; q++) acc[i][j][q] = 0.f;

    int selA = lane >> 3, rinA = lane & 7;
    #pragma unroll
    for (int kc = 0; kc < 64; kc += 16) {
        unsigned af[4][4], bf[4][2];
        #pragma unroll
        for (int mi = 0; mi < 4; mi++) {
            int m = wr * 64 + mi * 16 + (selA & 1) * 8 + rinA;
            unsigned off = (unsigned)(m * 128 + kc * 2 + (selA >> 1) * 16);
            off ^= (unsigned)((m & 7) << 4);
            ldsm_x4(af[mi][0], af[mi][1], af[mi][2], af[mi][3], baseA + off);
        }
        #pragma unroll
        for (int ni = 0; ni < 4; ni++) {
            int n = wc * 32 + ni * 8 + rinA;
            unsigned off = (unsigned)(n * 128 + kc * 2 + ((lane >> 3) & 1) * 16);
            off ^= (unsigned)((n & 7) << 4);
            ldsm_x2(bf[ni][0], bf[ni][1], baseB + off);
        }
        #pragma unroll
        for (int mi = 0; mi < 4; mi++)
            #pragma unroll
            for (int ni = 0; ni < 4; ni++)
                mma16816(acc[mi][ni], af[mi][0], af[mi][1], af[mi][2], af[mi][3],
                         bf[ni][0], bf[ni][1]);
    }

    int quad = lane & 3, rr = lane >> 2;
    #pragma unroll
    for (int mi = 0; mi < 4; mi++) {
        float s0 = 0.f, s1 = 0.f;
        #pragma unroll
        for (int ni = 0; ni < 4; ni++) {
            s0 += __expf(acc[mi][ni][0] * 5.0f) + __expf(acc[mi][ni][1] * 5.0f);
            s1 += __expf(acc[mi][ni][2] * 5.0f) + __expf(acc[mi][ni][3] * 5.0f);
        }
        s0 += __shfl_xor_sync(0xffffffffu, s0, 1);
        s0 += __shfl_xor_sync(0xffffffffu, s0, 2);
        s1 += __shfl_xor_sync(0xffffffffu, s1, 1);
        s1 += __shfl_xor_sync(0xffffffffu, s1, 2);
        if (quad == 0) {
            int row = r0 + wr * 64 + mi * 16 + rr;
            atomicAdd(&d_negS[s * BB + row], s0);
            atomicAdd(&d_negS[s * BB + row + 8], s1);
        }
    }
}

__global__ void k_final(const float* __restrict__ ui, const float* __restrict__ ii,
                        float* __restrict__ out) {
    __shared__ double sh[256];
    __shared__ double sh2[256];
    int tid = threadIdx.x;
    double isum = 0.0, clsum = 0.0;
    for (int i = tid; i < 8192; i += 256) {
        float a = ui[i], b2 = ii[i];
        isum += (double)a * a + (double)b2 * b2;
    }
    for (int i = tid; i < 2 * BB; i += 256) {
        float ng = d_negS[i];
        d_negS[i] = 0.f;                       // recycle for next replay
        float p  = expf(d_posS[i] * 5.0f);
        clsum += -(double)logf(p / (ng + 1e-8f) + 1e-8f);
    }
    sh[tid] = isum; sh2[tid] = clsum;
    __syncthreads();
    for (int o = 128; o; o >>= 1) {
        if (tid < o) { sh[tid] += sh[tid + o]; sh2[tid] += sh2[tid + o]; }
        __syncthreads();
    }
    if (tid == 0) {
        double kl = d_sums[0], bpr = d_sums[1], emb = d_sums[2];
        out[0] = (float)(bpr / 4096.0 + 0.01 * (kl / 150000.0));
        out[1] = (float)(0.1 * (sh2[0] / 4096.0));
        out[2] = (float)(1e-5 * emb);
        out[3] = (float)(1e-5 * sh[0]);
        d_sums[0] = 0.0; d_sums[1] = 0.0; d_sums[2] = 0.0;   // recycle
        d_cursor = 0;                                        // recycle
    }
}

// ---------------- launch ---------------------------------------------------
extern "C" void kernel_launch(void* const* d_in, const int* in_sizes, int n_in,
                              void* d_out, int out_size) {
    (void)n_in; (void)out_size;
    const float* user_emb = (const float*)d_in[0];
    const float* item_emb = (const float*)d_in[1];
    const float* user_int = (const float*)d_in[2];
    const float* item_int = (const float*)d_in[3];
    const float* lin_w    = (const float*)d_in[4];
    const float* lin_b    = (const float*)d_in[5];
    const float* eps      = (const float*)d_in[6];
    const int*   h        = (const int*)d_in[7];
    const int*   t        = (const int*)d_in[8];
    const int*   users    = (const int*)d_in[9];
    const int*   pos      = (const int*)d_in[10];
    const int*   neg      = (const int*)d_in[11];
    int E = in_sizes[7];
    float* out = (float*)d_out;

    int e4b = ((E >> 2) + 255) / 256;
    k_count<<<e4b, 256>>>((const int4*)h, h, E);
    k_scanfill<<<NBLK, 256>>>((const float4*)user_emb, (const float4*)item_emb);
    k_bin<<<e4b, 256>>>((const int4*)h, (const int4*)t, h, t, E);

    int gb = NN * 32 / 256;
    k_gather<0><<<gb, 256>>>((const float4*)user_emb, (const float4*)item_emb);
    k_gather<1><<<gb, 256>>>((const float4*)user_emb, (const float4*)item_emb);
    k_gather<2><<<gb, 256>>>((const float4*)user_emb, (const float4*)item_emb);

    k_kl<<<NBLK, 256>>>(lin_w, lin_b);
    k_bpr_emb<<<BB / 8, 256>>>(user_emb, item_emb, users, pos, neg);
    k_build_cl<<<dim3(BB / 16, 2), 128>>>(user_int, item_int, lin_w, lin_b, eps, users, pos);
    k_infonce_mma<<<dim3(32, 32, 2), 256>>>();
    k_final<<<1, 256>>>(user_int, item_int, out);
}

// round 16
// speedup vs baseline: 1.0097x; 1.0097x over previous
#include <cuda_runtime.h>
#include <cuda_fp16.h>
#include <cuda_bf16.h>
#include <math.h>

#define NU 50000
#define NI 100000
#define NN 150000
#define DD 64
#define BB 4096
#define EMAX 3150000
#define NBLK 586            // ceil(NN/256)

// ---------------- device scratch -------------------------------------------
__device__ float  d_deg[NN];            // dinv = deg^-0.5
__device__ float  d_rdeg[NN];           // sqrt(deg)
__device__ int    d_cnt[NN];            // counts -> cursors (reset by gather p0)
__device__ int    d_rowptr[NN];         // row start
__device__ int    d_rend[NN];           // row end
__device__ int    d_cursor = 0;         // global CSR allocation cursor
__device__ int    d_et[EMAX];           // CSR-sorted target ids
__device__ __half d_egoh[NN * DD];      // s0 = dinv * ego
__device__ __half d_curh[NN * DD];      // s1
__device__ __half d_nxth[NN * DD];      // s2
__device__ float  d_acc[NN * DD];
__device__ __half d_genH[2 * BB * DD];
__device__ __half d_intH[2 * BB * DD];
__device__ float  d_negS[2 * BB];       // zeroed by k_final after use
__device__ float  d_posS[2 * BB];
__device__ double d_sums[4];            // 0: kl, 1: bpr, 2: emb (zeroed by k_final)

__device__ __forceinline__ float softplus_f(float x) {
    return x > 0.f ? x + log1pf(expf(-x)) : log1pf(expf(x));
}

__device__ __forceinline__ unsigned smem_u32(const void* p) {
    return (unsigned)__cvta_generic_to_shared(p);
}

__device__ __forceinline__ void ldsm_x4(unsigned &r0, unsigned &r1, unsigned &r2, unsigned &r3, unsigned addr) {
    asm volatile("ldmatrix.sync.aligned.m8n8.x4.shared.b16 {%0,%1,%2,%3}, [%4];"
                 : "=r"(r0), "=r"(r1), "=r"(r2), "=r"(r3) : "r"(addr));
}
__device__ __forceinline__ void ldsm_x2(unsigned &r0, unsigned &r1, unsigned addr) {
    asm volatile("ldmatrix.sync.aligned.m8n8.x2.shared.b16 {%0,%1}, [%2];"
                 : "=r"(r0), "=r"(r1) : "r"(addr));
}
__device__ __forceinline__ void mma16816(float* c, unsigned a0, unsigned a1, unsigned a2, unsigned a3,
                                         unsigned b0, unsigned b1) {
    asm volatile("mma.sync.aligned.m16n8k16.row.col.f32.f16.f16.f32 "
                 "{%0,%1,%2,%3}, {%4,%5,%6,%7}, {%8,%9}, {%0,%1,%2,%3};"
                 : "+f"(c[0]), "+f"(c[1]), "+f"(c[2]), "+f"(c[3])
                 : "r"(a0), "r"(a1), "r"(a2), "r"(a3), "r"(b0), "r"(b1));
}

// ---------------- CSR build ------------------------------------------------
__global__ void k_count(const int4* __restrict__ h4, const int* __restrict__ h, int E) {
    int i = blockIdx.x * blockDim.x + threadIdx.x;
    int E4 = E >> 2;
    if (i < E4) {
        int4 q = __ldg(h4 + i);
        atomicAdd(&d_cnt[q.x], 1);
        atomicAdd(&d_cnt[q.y], 1);
        atomicAdd(&d_cnt[q.z], 1);
        atomicAdd(&d_cnt[q.w], 1);
    }
    int tail = E4 * 4 + i;
    if (i < (E & 3)) atomicAdd(&d_cnt[h[tail]], 1);
}

// block scan + atomic block base, then convert this block's ego rows to half.
__global__ void k_scanfill(const float4* __restrict__ ue, const float4* __restrict__ ie) {
    __shared__ int sh[256];
    __shared__ int sbase;
    __shared__ float sdeg[256];
    int tid = threadIdx.x;
    int idx = blockIdx.x * 256 + tid;
    int c = (idx < NN) ? d_cnt[idx] : 0;
    sh[tid] = c;
    __syncthreads();
    for (int o = 1; o < 256; o <<= 1) {
        int x = sh[tid];
        if (tid >= o) x += sh[tid - o];
        __syncthreads();
        sh[tid] = x;
        __syncthreads();
    }
    if (tid == 255) sbase = atomicAdd(&d_cursor, sh[255]);
    __syncthreads();
    float dinv = rsqrtf((float)c);
    if (idx < NN) {
        int p = sbase + sh[tid] - c;
        d_rowptr[idx] = p;
        d_rend[idx] = p + c;
        d_cnt[idx] = p;                 // cursor for binning
        d_deg[idx] = dinv;
        d_rdeg[idx] = sqrtf((float)c);
    }
    sdeg[tid] = dinv;
    __syncthreads();
    int base_node = blockIdx.x * 256;
    for (int i = tid; i < 4096; i += 256) {
        int node = base_node + (i >> 4);
        if (node >= NN) continue;
        int ch = i & 15;
        float4 v = (node < NU) ? __ldg(ue + (size_t)node * 16 + ch)
                               : __ldg(ie + (size_t)(node - NU) * 16 + ch);
        float s = sdeg[i >> 4];
        union { uint2 u; __half2 h[2]; } o;
        o.h[0] = __floats2half2_rn(s * v.x, s * v.y);
        o.h[1] = __floats2half2_rn(s * v.z, s * v.w);
        ((uint2*)d_egoh)[(size_t)node * 16 + ch] = o.u;
    }
}

__global__ void k_bin(const int4* __restrict__ h4, const int4* __restrict__ t4,
                      const int* __restrict__ h, const int* __restrict__ t, int E) {
    int i = blockIdx.x * blockDim.x + threadIdx.x;
    int E4 = E >> 2;
    if (i < E4) {
        int4 qh = __ldg(h4 + i);
        int4 qt = __ldg(t4 + i);
        d_et[atomicAdd(&d_cnt[qh.x], 1)] = qt.x;
        d_et[atomicAdd(&d_cnt[qh.y], 1)] = qt.y;
        d_et[atomicAdd(&d_cnt[qh.z], 1)] = qt.z;
        d_et[atomicAdd(&d_cnt[qh.w], 1)] = qt.w;
    }
    int tail = E4 * 4 + i;
    if (i < (E & 3)) d_et[atomicAdd(&d_cnt[h[tail]], 1)] = t[tail];
}

// ---------------- pull gather: warp/node, HADD2, indep idx pipeline --------
template<int PASS>
__global__ void k_gather(const float4* __restrict__ ue, const float4* __restrict__ ie) {
    int node = (blockIdx.x * blockDim.x + threadIdx.x) >> 5;
    int lane = threadIdx.x & 31;
    int sub = lane >> 3, ch = lane & 7;
    int beg = __ldg(&d_rowptr[node]);
    int end = __ldg(&d_rend[node]);
    const char* __restrict__ src =
        (PASS == 0) ? (const char*)d_egoh :
        (PASS == 1) ? (const char*)d_curh : (const char*)d_nxth;
    unsigned choff = (unsigned)ch << 4;
    __half2 z2 = __float2half2_rn(0.f);
    __half2 va0 = z2, va1 = z2, va2 = z2, va3 = z2;
    __half2 vb0 = z2, vb1 = z2, vb2 = z2, vb3 = z2;
    int e = beg + sub;
    int t0 = 0, t1 = 0;
    if (e < end) t0 = __ldg(&d_et[e]);
    if (e + 4 < end) t1 = __ldg(&d_et[e + 4]);
    while (e + 4 < end) {
        union { uint4 u; __half2 h[4]; } x0, x1;
        x0.u = __ldg((const uint4*)(src + (((unsigned)t0) << 7) + choff));
        x1.u = __ldg((const uint4*)(src + (((unsigned)t1) << 7) + choff));
        e += 8;
        int n0 = 0, n1 = 0;
        if (e < end)     n0 = __ldg(&d_et[e]);
        if (e + 4 < end) n1 = __ldg(&d_et[e + 4]);
        va0 = __hadd2(va0, x0.h[0]); va1 = __hadd2(va1, x0.h[1]);
        va2 = __hadd2(va2, x0.h[2]); va3 = __hadd2(va3, x0.h[3]);
        vb0 = __hadd2(vb0, x1.h[0]); vb1 = __hadd2(vb1, x1.h[1]);
        vb2 = __hadd2(vb2, x1.h[2]); vb3 = __hadd2(vb3, x1.h[3]);
        t0 = n0; t1 = n1;
    }
    if (e < end) {
        union { uint4 u; __half2 h[4]; } x0;
        x0.u = __ldg((const uint4*)(src + (((unsigned)t0) << 7) + choff));
        va0 = __hadd2(va0, x0.h[0]); va1 = __hadd2(va1, x0.h[1]);
        va2 = __hadd2(va2, x0.h[2]); va3 = __hadd2(va3, x0.h[3]);
    }
    float v[8];
    {
        float2 fa, fb;
        fa = __half22float2(va0); fb = __half22float2(vb0); v[0] = fa.x + fb.x; v[1] = fa.y + fb.y;
        fa = __half22float2(va1); fb = __half22float2(vb1); v[2] = fa.x + fb.x; v[3] = fa.y + fb.y;
        fa = __half22float2(va2); fb = __half22float2(vb2); v[4] = fa.x + fb.x; v[5] = fa.y + fb.y;
        fa = __half22float2(va3); fb = __half22float2(vb3); v[6] = fa.x + fb.x; v[7] = fa.y + fb.y;
    }
    // reduce across the 4 edge slots
    #pragma unroll
    for (int j = 0; j < 8; j++) {
        v[j] += __shfl_xor_sync(0xffffffffu, v[j], 8);
        v[j] += __shfl_xor_sync(0xffffffffu, v[j], 16);
    }
    float dinv = __ldg(&d_deg[node]);
    if (PASS == 0 && lane == 0) d_cnt[node] = 0;  // recycle for next replay
    if (sub != 0) return;
    if (PASS < 2) {
        float s = dinv * dinv;
        union { uint4 u; __half2 h[4]; } o;
        o.h[0] = __floats2half2_rn(s * v[0], s * v[1]);
        o.h[1] = __floats2half2_rn(s * v[2], s * v[3]);
        o.h[2] = __floats2half2_rn(s * v[4], s * v[5]);
        o.h[3] = __floats2half2_rn(s * v[6], s * v[7]);
        uint4* dst = (PASS == 0) ? (uint4*)d_curh : (uint4*)d_nxth;
        dst[(size_t)node * 8 + ch] = o.u;
    } else {
        float rd = __ldg(&d_rdeg[node]);
        union { uint4 u; __half2 h[4]; } a, b;
        a.u = __ldg((const uint4*)d_curh + (size_t)node * 8 + ch);
        b.u = __ldg((const uint4*)d_nxth + (size_t)node * 8 + ch);
        const float4* ego = (node < NU) ? (ue + (size_t)node * 16)
                                        : (ie + (size_t)(node - NU) * 16);
        float4 e0 = __ldg(ego + ch * 2);
        float4 e1 = __ldg(ego + ch * 2 + 1);
        float s12[8];
        {
            float2 f0 = __half22float2(a.h[0]), g0 = __half22float2(b.h[0]);
            float2 f1 = __half22float2(a.h[1]), g1 = __half22float2(b.h[1]);
            float2 f2 = __half22float2(a.h[2]), g2 = __half22float2(b.h[2]);
            float2 f3 = __half22float2(a.h[3]), g3 = __half22float2(b.h[3]);
            s12[0] = f0.x + g0.x; s12[1] = f0.y + g0.y;
            s12[2] = f1.x + g1.x; s12[3] = f1.y + g1.y;
            s12[4] = f2.x + g2.x; s12[5] = f2.y + g2.y;
            s12[6] = f3.x + g3.x; s12[7] = f3.y + g3.y;
        }
        float4 o0, o1;
        o0.x = e0.x + rd * s12[0] + dinv * v[0];
        o0.y = e0.y + rd * s12[1] + dinv * v[1];
        o0.z = e0.z + rd * s12[2] + dinv * v[2];
        o0.w = e0.w + rd * s12[3] + dinv * v[3];
        o1.x = e1.x + rd * s12[4] + dinv * v[4];
        o1.y = e1.y + rd * s12[5] + dinv * v[5];
        o1.z = e1.z + rd * s12[6] + dinv * v[6];
        o1.w = e1.w + rd * s12[7] + dinv * v[7];
        float4* ap = (float4*)(d_acc + (size_t)node * 64 + ch * 8);
        ap[0] = o0;
        ap[1] = o1;
    }
}

// ---------------- KL over all rows: lane-per-row, W broadcast --------------
__global__ __launch_bounds__(256) void k_kl(const float* __restrict__ lin_w,
                                            const float* __restrict__ lin_b) {
    __shared__ float sW[2048];   // [d][t] d*32+t
    __shared__ float sB[64];
    __shared__ float wsum[8];
    int tid = threadIdx.x;
    for (int i = tid; i < 2048; i += 256) sW[i] = lin_w[i];
    if (tid < 64) sB[tid] = lin_b[tid];
    __syncthreads();
    int row = blockIdx.x * 256 + tid;
    float kl = 0.f;
    if (row < NN) {
        const float4* ar = (const float4*)(d_acc + (size_t)row * 64);
        float4 c0[16];
        #pragma unroll
        for (int i = 0; i < 16; i++) c0[i] = __ldg(ar + i);   // all 16 in flight
        float sp[32];
        #pragma unroll
        for (int i = 0; i < 8; i++) {
            sp[4*i+0] = softplus_f(c0[i].x);
            sp[4*i+1] = softplus_f(c0[i].y);
            sp[4*i+2] = softplus_f(c0[i].z);
            sp[4*i+3] = softplus_f(c0[i].w);
        }
        #pragma unroll
        for (int dq = 0; dq < 16; dq++) {
            float am[4] = {c0[dq].x, c0[dq].y, c0[dq].z, c0[dq].w};
            #pragma unroll
            for (int dj = 0; dj < 4; dj++) {
                int d = dq * 4 + dj;
                float s = sB[d] + 1e-8f;
                #pragma unroll
                for (int t4 = 0; t4 < 8; t4++) {
                    float4 w = *(const float4*)&sW[d * 32 + t4 * 4];
                    s += sp[4*t4] * w.x + sp[4*t4+1] * w.y
                       + sp[4*t4+2] * w.z + sp[4*t4+3] * w.w;
                }
                float k = -0.5f * (1.f + 2.f * s - am[dj] * am[dj] - expf(2.f * s));
                if (isfinite(k)) kl += k;
            }
        }
    }
    #pragma unroll
    for (int o = 16; o; o >>= 1) kl += __shfl_xor_sync(0xffffffffu, kl, o);
    if ((tid & 31) == 0) wsum[tid >> 5] = kl;
    __syncthreads();
    if (tid == 0) {
        float s = 0.f;
        #pragma unroll
        for (int i = 0; i < 8; i++) s += wsum[i];
        atomicAdd(&d_sums[0], (double)s);
    }
}

__global__ void k_bpr_emb(const float* __restrict__ ue, const float* __restrict__ ie,
                          const int* __restrict__ users, const int* __restrict__ pos,
                          const int* __restrict__ neg) {
    __shared__ float sb[8], se[8];
    int w = threadIdx.x >> 5, lane = threadIdx.x & 31;
    int b = blockIdx.x * 8 + w;
    float bpr = 0.f, emb = 0.f;
    {
        int u = users[b], pi = pos[b], ni = neg[b];
        float u0 = d_acc[u * 64 + lane],         u1 = d_acc[u * 64 + 32 + lane];
        float p0 = d_acc[(NU + pi) * 64 + lane], p1 = d_acc[(NU + pi) * 64 + 32 + lane];
        float n0 = d_acc[(NU + ni) * 64 + lane], n1 = d_acc[(NU + ni) * 64 + 32 + lane];
        float dsc = (u0 * n0 + u1 * n1) - (u0 * p0 + u1 * p1);
        float r0 = ue[u * 64 + lane],  r1 = ue[u * 64 + 32 + lane];
        float q0 = ie[pi * 64 + lane], q1 = ie[pi * 64 + 32 + lane];
        float m0 = ie[ni * 64 + lane], m1 = ie[ni * 64 + 32 + lane];
        float sq = r0 * r0 + r1 * r1 + q0 * q0 + q1 * q1 + m0 * m0 + m1 * m1;
        #pragma unroll
        for (int o = 16; o; o >>= 1) {
            dsc += __shfl_xor_sync(0xffffffffu, dsc, o);
            sq  += __shfl_xor_sync(0xffffffffu, sq, o);
        }
        if (lane == 0) { bpr = softplus_f(dsc); emb = sq; }
    }
    if (lane == 0) { sb[w] = bpr; se[w] = emb; }
    __syncthreads();
    if (threadIdx.x == 0) {
        float s1 = 0.f, s2 = 0.f;
        for (int i = 0; i < 8; i++) { s1 += sb[i]; s2 += se[i]; }
        atomicAdd(&d_sums[1], (double)s1);
        atomicAdd(&d_sums[2], (double)s2);
    }
}

// ---------------- build CL rows: one warp per sample -----------------------
__global__ __launch_bounds__(128) void k_build_cl(
        const float* __restrict__ u_int_w, const float* __restrict__ i_int_w,
        const float* __restrict__ lin_w, const float* __restrict__ lin_b,
        const float* __restrict__ eps,
        const int* __restrict__ users, const int* __restrict__ pos) {
    __shared__ float sI[64 * 129];   // intent [d][k], pitch 129
    __shared__ float sW[64 * 33];    // lin_w  [d][t], pitch 33
    int tid = threadIdx.x;
    int s = blockIdx.y;
    const float* intent = s ? i_int_w : u_int_w;
    for (int i = tid; i < 8192; i += 128)
        sI[(i >> 7) * 129 + (i & 127)] = intent[i];
    for (int i = tid; i < 2048; i += 128)
        sW[(i >> 5) * 33 + (i & 31)] = lin_w[i];
    __syncthreads();

    int wid = tid >> 5, lane = tid & 31;
    float bb0 = __ldg(lin_b + lane), bb1 = __ldg(lin_b + 32 + lane);

    for (int it = 0; it < 4; it++) {
        int b = blockIdx.x * 16 + wid * 4 + it;
        int r = s ? (NU + pos[b]) : users[b];
        float a0 = d_acc[(size_t)r * 64 + lane];
        float a1 = d_acc[(size_t)r * 64 + 32 + lane];

        float lg0 = 0.f, lg1 = 0.f, lg2 = 0.f, lg3 = 0.f;
        #pragma unroll
        for (int d = 0; d < 64; d++) {
            float ad = __shfl_sync(0xffffffffu, (d < 32) ? a0 : a1, d & 31);
            const float* row = &sI[d * 129 + lane];
            lg0 += ad * row[0];
            lg1 += ad * row[32];
            lg2 += ad * row[64];
            lg3 += ad * row[96];
        }
        float mx = fmaxf(fmaxf(lg0, lg1), fmaxf(lg2, lg3));
        #pragma unroll
        for (int o = 16; o; o >>= 1) mx = fmaxf(mx, __shfl_xor_sync(0xffffffffu, mx, o));
        float p0 = expf(lg0 - mx), p1 = expf(lg1 - mx), p2 = expf(lg2 - mx), p3 = expf(lg3 - mx);
        float ps = p0 + p1 + p2 + p3;
        #pragma unroll
        for (int o = 16; o; o >>= 1) ps += __shfl_xor_sync(0xffffffffu, ps, o);
        float inv = 1.f / ps;
        p0 *= inv; p1 *= inv; p2 *= inv; p3 *= inv;

        float ov0 = 0.f, ov1 = 0.f;
        const float* r0p = &sI[lane * 129];
        const float* r1p = &sI[(lane + 32) * 129];
        #pragma unroll
        for (int k = 0; k < 32; k++) {
            float q0 = __shfl_sync(0xffffffffu, p0, k);
            float q1 = __shfl_sync(0xffffffffu, p1, k);
            float q2 = __shfl_sync(0xffffffffu, p2, k);
            float q3 = __shfl_sync(0xffffffffu, p3, k);
            ov0 += q0 * r0p[k] + q1 * r0p[32 + k] + q2 * r0p[64 + k] + q3 * r0p[96 + k];
            ov1 += q0 * r1p[k] + q1 * r1p[32 + k] + q2 * r1p[64 + k] + q3 * r1p[96 + k];
        }

        float sp = softplus_f(a0);
        float sd0 = 0.f, sd1 = 0.f;
        const float* w0p = &sW[lane * 33];
        const float* w1p = &sW[(lane + 32) * 33];
        #pragma unroll
        for (int t = 0; t < 32; t++) {
            float spt = __shfl_sync(0xffffffffu, sp, t);
            sd0 += spt * w0p[t];
            sd1 += spt * w1p[t];
        }
        sd0 += bb0 + 1e-8f;
        sd1 += bb1 + 1e-8f;
        float g0 = a0 + __ldg(eps + (size_t)r * 64 + lane) * sd0;
        float g1 = a1 + __ldg(eps + (size_t)r * 64 + 32 + lane) * sd1;

        float gn = g0 * g0 + g1 * g1;
        float on = ov0 * ov0 + ov1 * ov1;
        #pragma unroll
        for (int o = 16; o; o >>= 1) {
            gn += __shfl_xor_sync(0xffffffffu, gn, o);
            on += __shfl_xor_sync(0xffffffffu, on, o);
        }
        gn = rsqrtf(gn); on = rsqrtf(on);
        g0 *= gn; g1 *= gn; ov0 *= on; ov1 *= on;
        float pd = g0 * ov0 + g1 * ov1;
        #pragma unroll
        for (int o = 16; o; o >>= 1) pd += __shfl_xor_sync(0xffffffffu, pd, o);

        size_t ob = (size_t)(s * BB + b) * 64;
        d_genH[ob + lane] = __float2half(g0);
        d_genH[ob + 32 + lane] = __float2half(g1);
        d_intH[ob + lane] = __float2half(ov0);
        d_intH[ob + 32 + lane] = __float2half(ov1);
        if (lane == 0) d_posS[s * BB + b] = pd;
    }
}

// ---------------- InfoNCE denominators via HMMA ----------------------------
__global__ __launch_bounds__(256, 1) void k_infonce_mma() {
    __shared__ __align__(16) __half sA[128 * 64];
    __shared__ __align__(16) __half sB[128 * 64];
    int s = blockIdx.z;
    int r0 = blockIdx.x * 128;
    int c0 = blockIdx.y * 128;
    const uint4* __restrict__ A  = (const uint4*)(d_genH + (size_t)s * BB * 64);
    const uint4* __restrict__ Bm = (const uint4*)(d_intH + (size_t)s * BB * 64);
    int tid = threadIdx.x;
    unsigned baseA = smem_u32(sA), baseB = smem_u32(sB);

    for (int i = tid; i < 1024; i += 256) {
        int r = i >> 3, c = i & 7;
        unsigned off = (unsigned)(r * 128 + c * 16);
        off ^= (unsigned)((r & 7) << 4);
        *(uint4*)((char*)sA + off) = __ldg(A  + (size_t)(r0 + r) * 8 + c);
        *(uint4*)((char*)sB + off) = __ldg(Bm + (size_t)(c0 + r) * 8 + c);
    }
    __syncthreads();

    int wid = tid >> 5, lane = tid & 31;
    int wr = wid >> 2, wc = wid & 3;
    float acc[4][4][4];
    #pragma unroll
    for (int i = 0; i < 4; i++)
        #pragma unroll
        for (int j = 0; j < 4; j++)
            #pragma unroll
            for (int q = 0; q < 4; q++) acc[i][j][q] = 0.f;

    int selA = lane >> 3, rinA = lane & 7;
    #pragma unroll
    for (int kc = 0; kc < 64; kc += 16) {
        unsigned af[4][4], bf[4][2];
        #pragma unroll
        for (int mi = 0; mi < 4; mi++) {
            int m = wr * 64 + mi * 16 + (selA & 1) * 8 + rinA;
            unsigned off = (unsigned)(m * 128 + kc * 2 + (selA >> 1) * 16);
            off ^= (unsigned)((m & 7) << 4);
            ldsm_x4(af[mi][0], af[mi][1], af[mi][2], af[mi][3], baseA + off);
        }
        #pragma unroll
        for (int ni = 0; ni < 4; ni++) {
            int n = wc * 32 + ni * 8 + rinA;
            unsigned off = (unsigned)(n * 128 + kc * 2 + ((lane >> 3) & 1) * 16);
            off ^= (unsigned)((n & 7) << 4);
            ldsm_x2(bf[ni][0], bf[ni][1], baseB + off);
        }
        #pragma unroll
        for (int mi = 0; mi < 4; mi++)
            #pragma unroll
            for (int ni = 0; ni < 4; ni++)
                mma16816(acc[mi][ni], af[mi][0], af[mi][1], af[mi][2], af[mi][3],
                         bf[ni][0], bf[ni][1]);
    }

    int quad = lane & 3, rr = lane >> 2;
    #pragma unroll
    for (int mi = 0; mi < 4; mi++) {
        float s0 = 0.f, s1 = 0.f;
        #pragma unroll
        for (int ni = 0; ni < 4; ni++) {
            s0 += __expf(acc[mi][ni][0] * 5.0f) + __expf(acc[mi][ni][1] * 5.0f);
            s1 += __expf(acc[mi][ni][2] * 5.0f) + __expf(acc[mi][ni][3] * 5.0f);
        }
        s0 += __shfl_xor_sync(0xffffffffu, s0, 1);
        s0 += __shfl_xor_sync(0xffffffffu, s0, 2);
        s1 += __shfl_xor_sync(0xffffffffu, s1, 1);
        s1 += __shfl_xor_sync(0xffffffffu, s1, 2);
        if (quad == 0) {
            int row = r0 + wr * 64 + mi * 16 + rr;
            atomicAdd(&d_negS[s * BB + row], s0);
            atomicAdd(&d_negS[s * BB + row + 8], s1);
        }
    }
}

__global__ void k_final(const float* __restrict__ ui, const float* __restrict__ ii,
                        float* __restrict__ out) {
    __shared__ double sh[256];
    __shared__ double sh2[256];
    int tid = threadIdx.x;
    double isum = 0.0, clsum = 0.0;
    for (int i = tid; i < 8192; i += 256) {
        float a = ui[i], b2 = ii[i];
        isum += (double)a * a + (double)b2 * b2;
    }
    for (int i = tid; i < 2 * BB; i += 256) {
        float ng = d_negS[i];
        d_negS[i] = 0.f;                       // recycle for next replay
        float p  = expf(d_posS[i] * 5.0f);
        clsum += -(double)logf(p / (ng + 1e-8f) + 1e-8f);
    }
    sh[tid] = isum; sh2[tid] = clsum;
    __syncthreads();
    for (int o = 128; o; o >>= 1) {
        if (tid < o) { sh[tid] += sh[tid + o]; sh2[tid] += sh2[tid + o]; }
        __syncthreads();
    }
    if (tid == 0) {
        double kl = d_sums[0], bpr = d_sums[1], emb = d_sums[2];
        out[0] = (float)(bpr / 4096.0 + 0.01 * (kl / 150000.0));
        out[1] = (float)(0.1 * (sh2[0] / 4096.0));
        out[2] = (float)(1e-5 * emb);
        out[3] = (float)(1e-5 * sh[0]);
        d_sums[0] = 0.0; d_sums[1] = 0.0; d_sums[2] = 0.0;   // recycle
        d_cursor = 0;                                        // recycle
    }
}

// ---------------- launch ---------------------------------------------------
extern "C" void kernel_launch(void* const* d_in, const int* in_sizes, int n_in,
                              void* d_out, int out_size) {
    (void)n_in; (void)out_size;
    const float* user_emb = (const float*)d_in[0];
    const float* item_emb = (const float*)d_in[1];
    const float* user_int = (const float*)d_in[2];
    const float* item_int = (const float*)d_in[3];
    const float* lin_w    = (const float*)d_in[4];
    const float* lin_b    = (const float*)d_in[5];
    const float* eps      = (const float*)d_in[6];
    const int*   h        = (const int*)d_in[7];
    const int*   t        = (const int*)d_in[8];
    const int*   users    = (const int*)d_in[9];
    const int*   pos      = (const int*)d_in[10];
    const int*   neg      = (const int*)d_in[11];
    int E = in_sizes[7];
    float* out = (float*)d_out;

    int e4b = ((E >> 2) + 255) / 256;
    k_count<<<e4b, 256>>>((const int4*)h, h, E);
    k_scanfill<<<NBLK, 256>>>((const float4*)user_emb, (const float4*)item_emb);
    k_bin<<<e4b, 256>>>((const int4*)h, (const int4*)t, h, t, E);

    int gb = NN * 32 / 256;
    k_gather<0><<<gb, 256>>>((const float4*)user_emb, (const float4*)item_emb);
    k_gather<1><<<gb, 256>>>((const float4*)user_emb, (const float4*)item_emb);
    k_gather<2><<<gb, 256>>>((const float4*)user_emb, (const float4*)item_emb);

    k_kl<<<NBLK, 256>>>(lin_w, lin_b);
    k_bpr_emb<<<BB / 8, 256>>>(user_emb, item_emb, users, pos, neg);
    k_build_cl<<<dim3(BB / 16, 2), 128>>>(user_int, item_int, lin_w, lin_b, eps, users, pos);
    k_infonce_mma<<<dim3(32, 32, 2), 256>>>();
    k_final<<<1, 256>>>(user_int, item_int, out);
}